// round 15
// baseline (speedup 1.0000x reference)
#include <cuda_runtime.h>
#include <cuda_fp16.h>
#include <cstdint>

// Problem constants
#define BSZ 128
#define SDIM 1024
#define AD 128
#define HH 512
#define NR (HH / 2)            // 256 rounds of 2 steps per chain
#define OUT_T 513

// Grid/tiling: 64 CTAs, each runs TWO mt-chains (mt=2j, 2j+1) with shared weights
#define NCTA 64
#define NTHREADS 288           // 8 compute warps + 1 staging warp
#define CLUSTER 4
#define MT 32
#define NT 32

// SMEM (words of uint32=half2)
// XA [0,16384) ; XB [16384,32768) : per-chain x tiles, v11 internal layout
//   word(k2,b): o16=k2>>3, c2=k2&7 -> o16*128 + b*4 + (c2&3) + ((c2&4)?XHI:0)
// UA [32768,36864) ; UB [36864,40960): u_t 2048 | u_{t+1} 2048 (UHI=1024 within)
// RED [40960,51200): 8 warps x WS
#define XHI 8192
#define XBW 16384              // chain B x base (words)
#define UAW 32768
#define UBW 36864
#define UHI 1024
#define REDW 40960
#define RS 40
#define GMS (16 * RS)          // 640
#define WS (2 * GMS)           // 1280
#define MB_BYTE 204800         // mbar base byte offset (= 51200 words * 4)
#define SMEM_BYTES (MB_BYTE + 64)

// mbar byte offsets from MB_BYTE: XA_lo 0, XA_hi 8, XB_lo 16, XB_hi 24, UA 32, UB 40, P 48

// Global sync state (zero-init once; epochs monotonic across graph replays)
__device__ unsigned g_arrive[NCTA];
__device__ unsigned g_release;
__device__ __align__(128) unsigned g_flag[4][32][32];   // padded lines (R6 lesson)

// fp16 state double buffer: [parity][mt*16384 + rank-slice layout as v11]
__device__ __align__(16) uint32_t g_xbuf[2][4 * 16384];
// fp16 drive PAIRED: [round][mt][u_t 2048 | u_{t+1} 2048]
__device__ __align__(16) uint32_t g_ubuf[(size_t)NR * 4 * 4096];
// A^T / B^T in x-layout, per 32-col block
__device__ __align__(16) uint32_t g_colA[32 * 16384];
__device__ __align__(16) uint32_t g_colB[4 * 16384];
// Precomputed A^2 and A*B, fp32
__device__ float g_a2[SDIM * SDIM];
__device__ float g_ab[SDIM * AD];

__device__ __forceinline__ void grid_barrier(unsigned epoch, int bid, int tid)
{
    __syncthreads();
    if (tid == 0) {
        __threadfence();
        *((volatile unsigned*)&g_arrive[bid]) = epoch;
    }
    if (bid == 0) {
        if (tid < NCTA) {
            while ((int)(*((volatile unsigned*)&g_arrive[tid]) - epoch) < 0) { }
        }
        __syncthreads();
        if (tid == 0) {
            __threadfence();
            *((volatile unsigned*)&g_release) = epoch;
        }
    } else if (tid == 0) {
        while ((int)(*((volatile unsigned*)&g_release) - epoch) < 0) { }
    }
    __syncthreads();
    __threadfence();
}

// named barrier for the 8 compute warps only (warp 8 never joins)
__device__ __forceinline__ void barc()
{
    asm volatile("bar.sync 1, 256;" ::: "memory");
}

__device__ __forceinline__ uint32_t pack2(float x, float y)
{
    __half2 h = __floats2half2_rn(x, y);
    return *(uint32_t*)&h;
}

__device__ __forceinline__ void mma_f16(float* d,
                                        uint32_t a0, uint32_t a1, uint32_t a2, uint32_t a3,
                                        uint32_t b0, uint32_t b1)
{
    asm volatile("mma.sync.aligned.m16n8k16.row.col.f32.f16.f16.f32 "
                 "{%0,%1,%2,%3}, {%4,%5,%6,%7}, {%8,%9}, {%0,%1,%2,%3};"
                 : "+f"(d[0]), "+f"(d[1]), "+f"(d[2]), "+f"(d[3])
                 : "r"(a0), "r"(a1), "r"(a2), "r"(a3), "r"(b0), "r"(b1));
}

__device__ __forceinline__ void bulk_mc(uint32_t dst_smem, const void* src,
                                        uint32_t bytes, uint32_t mbar, uint16_t mask)
{
    asm volatile("cp.async.bulk.shared::cluster.global.mbarrier::complete_tx::bytes"
                 ".multicast::cluster [%0], [%1], %2, [%3], %4;"
                 :: "r"(dst_smem), "l"(src), "r"(bytes), "r"(mbar), "h"(mask)
                 : "memory");
}

__device__ __forceinline__ void bulk_cp(uint32_t dst_smem, const void* src,
                                        uint32_t bytes, uint32_t mbar)
{
    asm volatile("cp.async.bulk.shared::cluster.global.mbarrier::complete_tx::bytes"
                 " [%0], [%1], %2, [%3];"
                 :: "r"(dst_smem), "l"(src), "r"(bytes), "r"(mbar)
                 : "memory");
}

__device__ __forceinline__ void mbar_expect(uint32_t mbar, uint32_t bytes)
{
    asm volatile("mbarrier.arrive.expect_tx.shared.b64 _, [%0], %1;"
                 :: "r"(mbar), "r"(bytes) : "memory");
}

__device__ __forceinline__ void mbar_wait(uint32_t mbar, uint32_t parity)
{
    uint32_t done;
    asm volatile("{\n\t.reg .pred p;\n\t"
                 "mbarrier.try_wait.parity.acquire.cta.shared::cta.b64 p, [%1], %2;\n\t"
                 "selp.b32 %0, 1, 0, p;\n\t}"
                 : "=r"(done) : "r"(mbar), "r"(parity) : "memory");
    if (!done) {
        asm volatile("{\n\t.reg .pred P1;\n\t"
                     "W%=:\n\t"
                     "mbarrier.try_wait.parity.acquire.cta.shared::cta.b64 P1, [%0], %1, 0x989680;\n\t"
                     "@P1 bra.uni D%=;\n\t"
                     "bra.uni W%=;\n\t"
                     "D%=:\n\t}"
                     :: "r"(mbar), "r"(parity) : "memory");
    }
}

extern "C" __global__ void __launch_bounds__(NTHREADS, 1) __cluster_dims__(CLUSTER, 1, 1)
ssm_v13_kernel(const float* __restrict__ x0, const float* __restrict__ u,
               const float* __restrict__ A, const float* __restrict__ Bm,
               float* __restrict__ out)
{
    extern __shared__ uint32_t sm[];
    float* red = (float*)(sm + REDW);

    const int tid = threadIdx.x;
    const int bid = blockIdx.x;
    const int j = bid >> 5;             // 0..1
    const int nt = bid & 31;
    const int mtA = 2 * j, mtB = 2 * j + 1;
    const int m0A = mtA * MT, m0B = mtB * MT;
    const int n0 = nt * NT;
    const int w = tid >> 5;             // 0..8 (8 = staging warp)
    const int lane = tid & 31;
    const int g = lane >> 2;
    const int c = lane & 3;
    const int ss = w & 1;               // compute warps only
    const int kg = (w >> 1) & 3;        // k-quarter (compute warps)
    const int gtid = bid * NTHREADS + tid;

    uint32_t rank;
    asm("mov.u32 %0, %%cluster_ctarank;" : "=r"(rank));

    const uint32_t smb = (uint32_t)__cvta_generic_to_shared(sm);
    const uint32_t mXAlo = smb + MB_BYTE + 0;
    const uint32_t mXAhi = smb + MB_BYTE + 8;
    const uint32_t mXBlo = smb + MB_BYTE + 16;
    const uint32_t mXBhi = smb + MB_BYTE + 24;
    const uint32_t mUA   = smb + MB_BYTE + 32;
    const uint32_t mUB   = smb + MB_BYTE + 40;
    const uint32_t mP    = smb + MB_BYTE + 48;

    const unsigned base = *((volatile unsigned*)&g_release);

    if (tid == 0) {
#pragma unroll
        for (int i = 0; i < 7; i++)
            asm volatile("mbarrier.init.shared.b64 [%0], %1;"
                         :: "r"(smb + MB_BYTE + i * 8), "r"(1) : "memory");
    }
    __syncthreads();
    asm volatile("barrier.cluster.arrive.aligned;" ::: "memory");
    asm volatile("barrier.cluster.wait.aligned;" ::: "memory");

    // ---- init: u -> fp16 ubuf, paired per round ----
    for (int jj = gtid; jj < HH * BSZ * (AD / 4); jj += NCTA * NTHREADS) {
        int a4 = jj & 31;
        int b = (jj >> 5) & 127;
        int t = jj >> 12;
        float4 v = *(const float4*)(u + ((size_t)b * HH + t) * AD + a4 * 4);
        int umt = b >> 5, bl = b & 31;
        int k2 = a4 * 2, o16u = k2 >> 3, c2 = k2 & 7;
        size_t idx = ((size_t)(t >> 1) * 4 + umt) * 4096 + (size_t)(t & 1) * 2048
                   + (size_t)o16u * 128 + (size_t)bl * 4 + (c2 & 3)
                   + ((c2 & 4) ? UHI : 0);
        *(uint2*)(g_ubuf + idx) = make_uint2(pack2(v.x, v.y), pack2(v.z, v.w));
    }
    // ---- init: xbuf[0] = fp16(x0); out[:,0,:] = x0 ----
    for (int jj = gtid; jj < BSZ * (SDIM / 4); jj += NCTA * NTHREADS) {
        int s4c = jj & 255;
        int b = jj >> 8;
        float4 v = ((const float4*)x0)[jj];
        ((float4*)out)[(size_t)b * OUT_T * (SDIM / 4) + s4c] = v;
        int xmt = b >> 5, bl = b & 31;
        int k2 = s4c * 2, o16 = k2 >> 3, c2 = k2 & 7;
        size_t idx = (size_t)xmt * 16384 + (size_t)o16 * 128 + (size_t)bl * 4
                   + (c2 & 3) + ((c2 & 4) ? XHI : 0);
        *(uint2*)(g_xbuf[0] + idx) = make_uint2(pack2(v.x, v.y), pack2(v.z, v.w));
    }
    // ---- init: colA/colB (transposed operands for A2/AB precompute) ----
    for (int jj = gtid; jj < 512 * 1024; jj += NCTA * NTHREADS) {
        int k = jj & 1023, j2 = jj >> 10;
        float v0 = A[(size_t)(2 * j2) * SDIM + k];
        float v1 = A[(size_t)(2 * j2 + 1) * SDIM + k];
        int kb = k >> 5, kcol = k & 31, o16 = j2 >> 3, c2 = j2 & 7;
        g_colA[(size_t)kb * 16384 + o16 * 128 + kcol * 4 + (c2 & 3)
               + ((c2 & 4) ? 8192 : 0)] = pack2(v0, v1);
    }
    for (int jj = gtid; jj < 512 * 128; jj += NCTA * NTHREADS) {
        int ku = jj & 127, j2 = jj >> 7;
        float v0 = Bm[(size_t)(2 * j2) * AD + ku];
        float v1 = Bm[(size_t)(2 * j2 + 1) * AD + ku];
        int kb = ku >> 5, kcol = ku & 31, o16 = j2 >> 3, c2 = j2 & 7;
        g_colB[(size_t)kb * 16384 + o16 * 128 + kcol * 4 + (c2 & 3)
               + ((c2 & 4) ? 8192 : 0)] = pack2(v0, v1);
    }

    // ---- fp16 A and B weights (compute warps only; shared by both chains) ----
    uint32_t axA[16][4], auB[2][4];
    const int srow = n0 + ss * 16 + g;
    if (tid < 256) {
#pragma unroll
        for (int i = 0; i < 16; i++) {
            int kb = kg * 256 + i * 16 + 2 * c;
            const float* r0 = A + (size_t)srow * SDIM;
            const float* r8 = A + (size_t)(srow + 8) * SDIM;
            axA[i][0] = pack2(r0[kb],     r0[kb + 1]);
            axA[i][1] = pack2(r8[kb],     r8[kb + 1]);
            axA[i][2] = pack2(r0[kb + 8], r0[kb + 9]);
            axA[i][3] = pack2(r8[kb + 8], r8[kb + 9]);
        }
#pragma unroll
        for (int jq = 0; jq < 2; jq++) {
            int kb = kg * 32 + jq * 16 + 2 * c;
            const float* r0 = Bm + (size_t)srow * AD;
            const float* r8 = Bm + (size_t)(srow + 8) * AD;
            auB[jq][0] = pack2(r0[kb],     r0[kb + 1]);
            auB[jq][1] = pack2(r8[kb],     r8[kb + 1]);
            auB[jq][2] = pack2(r0[kb + 8], r0[kb + 9]);
            auB[jq][3] = pack2(r8[kb + 8], r8[kb + 9]);
        }
    }

    grid_barrier(base + 1, bid, tid);

    // ---- precompute A2 (2x8 blocks) + AB (2 blocks): this CTA covers mtA,mtB ----
    for (int pr = 0; pr < 18; pr++) {
        int mtp = 2 * j + (pr >= 9);
        int blk = (pr >= 9) ? pr - 9 : pr;
        if (tid == 0) {
            mbar_expect(mP, 65536);
            const uint32_t* src = (blk < 8)
                ? g_colA + (size_t)(mtp * 8 + blk) * 16384
                : g_colB + (size_t)mtp * 16384;
            bulk_cp(smb, src, 65536, mP);
        }
        float d[4][4];
#pragma unroll
        for (int nn = 0; nn < 4; nn++)
#pragma unroll
            for (int e = 0; e < 4; e++) d[nn][e] = 0.0f;

        mbar_wait(mP, (uint32_t)(pr & 1));
        if (tid < 256) {
            const uint32_t* xs = sm + kg * 2048 + g * 4 + c;
#pragma unroll
            for (int i = 0; i < 16; i++) {
#pragma unroll
                for (int nn = 0; nn < 4; nn++) {
                    uint32_t b0 = xs[i * 128 + nn * 32];
                    uint32_t b1 = xs[i * 128 + nn * 32 + XHI];
                    mma_f16(d[nn], axA[i][0], axA[i][1], axA[i][2], axA[i][3], b0, b1);
                }
            }
            int rb = w * WS + g * RS + 2 * c;
#pragma unroll
            for (int nn = 0; nn < 4; nn++) {
                *(float2*)(red + rb + nn * 8) = make_float2(d[nn][0], d[nn][1]);
                *(float2*)(red + rb + 8 * RS + nn * 8) = make_float2(d[nn][2], d[nn][3]);
            }
        }
        __syncthreads();
        if (tid < 256) {
            int b = tid >> 3;
            int s4 = (tid & 7) * 4;
            int ssr = s4 >> 4;
            float acc[4] = {0.f, 0.f, 0.f, 0.f};
#pragma unroll
            for (int kk = 0; kk < 4; kk++) {
                int wb = (kk * 2 + ssr) * WS + b;
#pragma unroll
                for (int i = 0; i < 4; i++)
                    acc[i] += red[wb + ((s4 + i) & 15) * RS];
            }
            if (blk < 8) {
                int kb = mtp * 8 + blk;
#pragma unroll
                for (int i = 0; i < 4; i++)
                    g_a2[(size_t)(n0 + s4 + i) * SDIM + kb * 32 + b] = acc[i];
            } else {
#pragma unroll
                for (int i = 0; i < 4; i++)
                    g_ab[(size_t)(n0 + s4 + i) * AD + mtp * 32 + b] = acc[i];
            }
        }
        __syncthreads();
    }

    grid_barrier(base + 2, bid, tid);

    // ---- fp16 A2 and AB weights ----
    uint32_t ax2[16][4], auAB[2][4];
    if (tid < 256) {
#pragma unroll
        for (int i = 0; i < 16; i++) {
            int kb = kg * 256 + i * 16 + 2 * c;
            const float* r0 = g_a2 + (size_t)srow * SDIM;
            const float* r8 = g_a2 + (size_t)(srow + 8) * SDIM;
            ax2[i][0] = pack2(r0[kb],     r0[kb + 1]);
            ax2[i][1] = pack2(r8[kb],     r8[kb + 1]);
            ax2[i][2] = pack2(r0[kb + 8], r0[kb + 9]);
            ax2[i][3] = pack2(r8[kb + 8], r8[kb + 9]);
        }
#pragma unroll
        for (int jq = 0; jq < 2; jq++) {
            int kb = kg * 32 + jq * 16 + 2 * c;
            const float* r0 = g_ab + (size_t)srow * AD;
            const float* r8 = g_ab + (size_t)(srow + 8) * AD;
            auAB[jq][0] = pack2(r0[kb],     r0[kb + 1]);
            auAB[jq][1] = pack2(r8[kb],     r8[kb + 1]);
            auAB[jq][2] = pack2(r0[kb + 8], r0[kb + 9]);
            auAB[jq][3] = pack2(r8[kb + 8], r8[kb + 9]);
        }
    }
    __syncthreads();

    // ---- bootstrap: round-0 staging for both chains ----
    if (tid == 0) {
        asm volatile("fence.proxy.async;" ::: "memory");
        mbar_expect(mXAlo, 32768); mbar_expect(mXAhi, 32768); mbar_expect(mUA, 16384);
        mbar_expect(mXBlo, 32768); mbar_expect(mXBhi, 32768); mbar_expect(mUB, 16384);
        bulk_mc(smb + rank * 16384u,
                g_xbuf[0] + (size_t)mtA * 16384 + (size_t)rank * 4096,
                16384, (rank & 1) ? mXAhi : mXAlo, 0xF);
        bulk_mc(smb + 65536u + rank * 16384u,
                g_xbuf[0] + (size_t)mtB * 16384 + (size_t)rank * 4096,
                16384, (rank & 1) ? mXBhi : mXBlo, 0xF);
        if (rank == 3) {
            bulk_mc(smb + UAW * 4u, g_ubuf + (size_t)mtA * 4096, 16384, mUA, 0xF);
            bulk_mc(smb + UBW * 4u, g_ubuf + (size_t)mtB * 4096, 16384, mUB, 0xF);
        }
    }

    if (tid < 256) {
        // ================= COMPUTE WARPS =================
        for (int r = 0; r < NR; r++) {
            const uint32_t par = (uint32_t)(r & 1);
#pragma unroll
            for (int ch = 0; ch < 2; ch++) {
                const uint32_t xw = ch ? XBW : 0;
                const uint32_t uw = ch ? UBW : UAW;
                const uint32_t mxlo = ch ? mXBlo : mXAlo;
                const uint32_t mxhi = ch ? mXBhi : mXAhi;
                const uint32_t mu = ch ? mUB : mUA;
                const int mt = ch ? mtB : mtA;
                const int m0 = ch ? m0B : m0A;

                float d1[4][4], d2[4][4];
#pragma unroll
                for (int nn = 0; nn < 4; nn++)
#pragma unroll
                    for (int e = 0; e < 4; e++) { d1[nn][e] = 0.f; d2[nn][e] = 0.f; }

                mbar_wait((kg >= 2) ? mxhi : mxlo, par);
                {
                    const uint32_t* xs = sm + xw + kg * 2048 + g * 4 + c;
#pragma unroll
                    for (int i = 0; i < 16; i++) {
#pragma unroll
                        for (int nn = 0; nn < 4; nn++) {
                            uint32_t b0 = xs[i * 128 + nn * 32];
                            uint32_t b1 = xs[i * 128 + nn * 32 + XHI];
                            mma_f16(d1[nn], axA[i][0], axA[i][1], axA[i][2], axA[i][3], b0, b1);
                            mma_f16(d2[nn], ax2[i][0], ax2[i][1], ax2[i][2], ax2[i][3], b0, b1);
                        }
                    }
                }
                mbar_wait(mu, par);
                {
                    const uint32_t* us = sm + uw + kg * 256 + g * 4 + c;
#pragma unroll
                    for (int jq = 0; jq < 2; jq++) {
#pragma unroll
                        for (int nn = 0; nn < 4; nn++) {
                            uint32_t b0 = us[jq * 128 + nn * 32];
                            uint32_t b1 = us[jq * 128 + nn * 32 + UHI];
                            mma_f16(d1[nn], auB[jq][0], auB[jq][1], auB[jq][2], auB[jq][3], b0, b1);
                            mma_f16(d2[nn], auAB[jq][0], auAB[jq][1], auAB[jq][2], auAB[jq][3], b0, b1);
                            uint32_t c0 = us[2048 + jq * 128 + nn * 32];
                            uint32_t c1 = us[2048 + jq * 128 + nn * 32 + UHI];
                            mma_f16(d2[nn], auB[jq][0], auB[jq][1], auB[jq][2], auB[jq][3], c0, c1);
                        }
                    }
                }
                // partials
                {
                    int rb = w * WS + g * RS + 2 * c;
#pragma unroll
                    for (int nn = 0; nn < 4; nn++) {
                        *(float2*)(red + rb + nn * 8) = make_float2(d1[nn][0], d1[nn][1]);
                        *(float2*)(red + rb + 8 * RS + nn * 8) = make_float2(d1[nn][2], d1[nn][3]);
                        *(float2*)(red + rb + GMS + nn * 8) = make_float2(d2[nn][0], d2[nn][1]);
                        *(float2*)(red + rb + GMS + 8 * RS + nn * 8) = make_float2(d2[nn][2], d2[nn][3]);
                    }
                }
                barc();
                // reduce + outputs + next state
                {
                    int b = tid >> 3;
                    int s4 = (tid & 7) * 4;
                    int ssr = s4 >> 4;
                    float a1[4] = {0.f, 0.f, 0.f, 0.f};
                    float a2v[4] = {0.f, 0.f, 0.f, 0.f};
#pragma unroll
                    for (int kk = 0; kk < 4; kk++) {
                        int wb = (kk * 2 + ssr) * WS + b;
#pragma unroll
                        for (int i = 0; i < 4; i++) {
                            a1[i] += red[wb + ((s4 + i) & 15) * RS];
                            a2v[i] += red[wb + GMS + ((s4 + i) & 15) * RS];
                        }
                    }
                    float* op1 = out + ((size_t)(m0 + b) * OUT_T + (2 * r + 1)) * SDIM + n0 + s4;
                    *(float4*)op1 = make_float4(a1[0], a1[1], a1[2], a1[3]);
                    float* op2 = out + ((size_t)(m0 + b) * OUT_T + (2 * r + 2)) * SDIM + n0 + s4;
                    *(float4*)op2 = make_float4(a2v[0], a2v[1], a2v[2], a2v[3]);

                    int k2 = (n0 + s4) >> 1;
                    int o16 = k2 >> 3, c2 = k2 & 7;
                    size_t idx = (size_t)mt * 16384 + (size_t)o16 * 128 + (size_t)b * 4
                               + (c2 & 3) + ((c2 & 4) ? XHI : 0);
                    uint32_t* xp = g_xbuf[(r + 1) & 1] + idx;
                    uint32_t w0 = pack2(a2v[0], a2v[1]);
                    uint32_t w1 = pack2(a2v[2], a2v[3]);
                    asm volatile("st.global.cg.v2.b32 [%0], {%1,%2};"
                                 :: "l"(xp), "r"(w0), "r"(w1) : "memory");
                }
                __threadfence();
                barc();
                if (tid == 0)
                    *((volatile unsigned*)&g_flag[mt][nt][0]) = base + 3 + r;
            }
        }
        if (bid == 0 && tid == 0) {
            __threadfence();
            *((volatile unsigned*)&g_release) = base + 3 + NR;
        }
    } else {
        // ================= STAGING WARP (warp 8) =================
        for (int r = 0; r + 1 < NR; r++) {
            unsigned want = base + 3 + r;
#pragma unroll
            for (int ch = 0; ch < 2; ch++) {
                const int mt = ch ? mtB : mtA;
                while ((int)(*((volatile unsigned*)&g_flag[mt][lane][0]) - want) < 0) { }
                __syncwarp();
                if (lane == 0) {
                    __threadfence();
                    asm volatile("fence.proxy.async;" ::: "memory");
                    const uint32_t mxlo = ch ? mXBlo : mXAlo;
                    const uint32_t mxhi = ch ? mXBhi : mXAhi;
                    const uint32_t mu = ch ? mUB : mUA;
                    mbar_expect(mxlo, 32768);
                    mbar_expect(mxhi, 32768);
                    mbar_expect(mu, 16384);
                    bulk_mc(smb + (ch ? 65536u : 0u) + rank * 16384u,
                            g_xbuf[(r + 1) & 1] + (size_t)mt * 16384 + (size_t)rank * 4096,
                            16384, (rank & 1) ? mxhi : mxlo, 0xF);
                    if (rank == 3)
                        bulk_mc(smb + (ch ? UBW : UAW) * 4u,
                                g_ubuf + ((size_t)(r + 1) * 4 + mt) * 4096,
                                16384, mu, 0xF);
                }
                __syncwarp();
            }
        }
    }
}

extern "C" void kernel_launch(void* const* d_in, const int* in_sizes, int n_in,
                              void* d_out, int out_size)
{
    const float* x0 = (const float*)d_in[0];
    const float* u  = (const float*)d_in[1];
    const float* A  = (const float*)d_in[2];
    const float* Bm = (const float*)d_in[3];
    float* out = (float*)d_out;

    cudaFuncSetAttribute(ssm_v13_kernel,
                         cudaFuncAttributeMaxDynamicSharedMemorySize, SMEM_BYTES);

    ssm_v13_kernel<<<NCTA, NTHREADS, SMEM_BYTES>>>(x0, u, A, Bm, out);
}

// round 16
// speedup vs baseline: 2.0177x; 2.0177x over previous
#include <cuda_runtime.h>
#include <cuda_fp16.h>
#include <cstdint>

#define BSZ 128
#define SDIM 1024
#define AD 128
#define HH 512
#define NRF 170               // full 3-step rounds (steps 1..510); +1 final 2-step
#define NRT 171
#define OUT_T 513

#define NCTA 128
#define NTHREADS 256
#define CLUSTER 4
#define MT 32
#define NT 32

// SMEM words (uint32=half2): X [0,16384) v11 layout (XHI=8192 hi-half)
// U [16384,22528): slot j at +j*2048, hi +1024 | WA [22528,38912)
// slab0 [38912,+5120) slab1 [44032,+5120) | mbar @ byte 196608
#define XHI 8192
#define UWB 16384
#define WAW 22528
#define SL0 38912
#define SL1 44032
#define RS 40
#define GMS 640
#define MBB 196608
#define SMEM_BYTES (MBB + 64)

__device__ unsigned g_arrive[NCTA];
__device__ unsigned g_release;
__device__ __align__(128) unsigned g_flag[4][32][32];

__device__ __align__(16) uint32_t g_xbuf[2][4 * 16384];
__device__ __align__(16) uint32_t g_ubuf[(size_t)NRT * 4 * 6144];
__device__ __align__(16) uint32_t g_colA[32 * 16384];
__device__ __align__(16) uint32_t g_colB[4 * 16384];
__device__ __align__(16) uint32_t g_colA2[32 * 16384];
__device__ __align__(16) uint32_t g_colAB[4 * 16384];
__device__ float g_a2[SDIM * SDIM];
__device__ float g_ab[SDIM * AD];
__device__ float g_a3[SDIM * SDIM];
__device__ float g_a2b[SDIM * AD];

__device__ __forceinline__ void grid_barrier(unsigned epoch, int bid, int tid)
{
    __syncthreads();
    if (tid == 0) { __threadfence(); *((volatile unsigned*)&g_arrive[bid]) = epoch; }
    if (bid == 0) {
        if (tid < NCTA)
            while ((int)(*((volatile unsigned*)&g_arrive[tid]) - epoch) < 0) { }
        __syncthreads();
        if (tid == 0) { __threadfence(); *((volatile unsigned*)&g_release) = epoch; }
    } else if (tid == 0) {
        while ((int)(*((volatile unsigned*)&g_release) - epoch) < 0) { }
    }
    __syncthreads();
    __threadfence();
}

__device__ __forceinline__ uint32_t pack2(float x, float y)
{
    __half2 h = __floats2half2_rn(x, y);
    return *(uint32_t*)&h;
}

__device__ __forceinline__ void mma_f16(float* d, uint32_t a0, uint32_t a1,
                                        uint32_t a2, uint32_t a3, uint32_t b0, uint32_t b1)
{
    asm volatile("mma.sync.aligned.m16n8k16.row.col.f32.f16.f16.f32 "
                 "{%0,%1,%2,%3}, {%4,%5,%6,%7}, {%8,%9}, {%0,%1,%2,%3};"
                 : "+f"(d[0]), "+f"(d[1]), "+f"(d[2]), "+f"(d[3])
                 : "r"(a0), "r"(a1), "r"(a2), "r"(a3), "r"(b0), "r"(b1));
}

__device__ __forceinline__ void bulk_mc(uint32_t dst, const void* src, uint32_t bytes,
                                        uint32_t mbar, uint16_t mask)
{
    asm volatile("cp.async.bulk.shared::cluster.global.mbarrier::complete_tx::bytes"
                 ".multicast::cluster [%0], [%1], %2, [%3], %4;"
                 :: "r"(dst), "l"(src), "r"(bytes), "r"(mbar), "h"(mask) : "memory");
}

__device__ __forceinline__ void bulk_cp(uint32_t dst, const void* src, uint32_t bytes,
                                        uint32_t mbar)
{
    asm volatile("cp.async.bulk.shared::cluster.global.mbarrier::complete_tx::bytes"
                 " [%0], [%1], %2, [%3];"
                 :: "r"(dst), "l"(src), "r"(bytes), "r"(mbar) : "memory");
}

__device__ __forceinline__ void mbar_expect(uint32_t mbar, uint32_t bytes)
{
    asm volatile("mbarrier.arrive.expect_tx.shared.b64 _, [%0], %1;"
                 :: "r"(mbar), "r"(bytes) : "memory");
}

__device__ __forceinline__ void mbar_wait(uint32_t mbar, uint32_t parity)
{
    uint32_t done;
    asm volatile("{\n\t.reg .pred p;\n\t"
                 "mbarrier.try_wait.parity.acquire.cta.shared::cta.b64 p, [%1], %2;\n\t"
                 "selp.b32 %0, 1, 0, p;\n\t}" : "=r"(done) : "r"(mbar), "r"(parity) : "memory");
    if (!done) {
        asm volatile("{\n\t.reg .pred P1;\n\t"
                     "W%=:\n\t"
                     "mbarrier.try_wait.parity.acquire.cta.shared::cta.b64 P1, [%0], %1, 0x989680;\n\t"
                     "@P1 bra.uni D%=;\n\t bra.uni W%=;\n\t D%=:\n\t}"
                     :: "r"(mbar), "r"(parity) : "memory");
    }
}

// one precompute block-round set: dstM = A*srcM blocks, dstU = A*srcU
__device__ __forceinline__ void precomp9(const uint32_t (&axA)[16][4],
    const uint32_t* colM, const uint32_t* colU, float* dstM, float* dstU,
    uint32_t* sm, float* red0, uint32_t smb, uint32_t mbarP,
    int mt, int n0, int tid, int w, int kg, int g, int c, int parb)
{
    for (int pr = 0; pr < 9; pr++) {
        if (tid == 0) {
            mbar_expect(mbarP, 65536);
            const uint32_t* src = (pr < 8) ? colM + (size_t)(mt * 8 + pr) * 16384
                                           : colU + (size_t)mt * 16384;
            bulk_cp(smb, src, 65536, mbarP);
        }
        float d[4][4];
#pragma unroll
        for (int nn = 0; nn < 4; nn++)
#pragma unroll
            for (int e = 0; e < 4; e++) d[nn][e] = 0.f;
        mbar_wait(mbarP, (uint32_t)((parb + pr) & 1));
        const uint32_t* xs = sm + kg * 2048 + g * 4 + c;
#pragma unroll
        for (int i = 0; i < 16; i++)
#pragma unroll
            for (int nn = 0; nn < 4; nn++)
                mma_f16(d[nn], axA[i][0], axA[i][1], axA[i][2], axA[i][3],
                        xs[i * 128 + nn * 32], xs[i * 128 + nn * 32 + XHI]);
        int rb = w * GMS + g * RS + 2 * c;
#pragma unroll
        for (int nn = 0; nn < 4; nn++) {
            *(float2*)(red0 + rb + nn * 8) = make_float2(d[nn][0], d[nn][1]);
            *(float2*)(red0 + rb + 8 * RS + nn * 8) = make_float2(d[nn][2], d[nn][3]);
        }
        __syncthreads();
        int b = tid >> 3, s4 = (tid & 7) * 4, ssr = s4 >> 4;
        float acc[4] = {0.f, 0.f, 0.f, 0.f};
#pragma unroll
        for (int kk = 0; kk < 4; kk++) {
            int wb = (kk * 2 + ssr) * GMS + b;
#pragma unroll
            for (int i = 0; i < 4; i++) acc[i] += red0[wb + ((s4 + i) & 15) * RS];
        }
        if (pr < 8) {
#pragma unroll
            for (int i = 0; i < 4; i++)
                dstM[(size_t)(n0 + s4 + i) * SDIM + (mt * 8 + pr) * 32 + b] = acc[i];
        } else {
#pragma unroll
            for (int i = 0; i < 4; i++)
                dstU[(size_t)(n0 + s4 + i) * AD + mt * 32 + b] = acc[i];
        }
        __syncthreads();
    }
}

extern "C" __global__ void __launch_bounds__(NTHREADS, 1) __cluster_dims__(CLUSTER, 1, 1)
ssm_v16_kernel(const float* __restrict__ x0, const float* __restrict__ u,
               const float* __restrict__ A, const float* __restrict__ Bm,
               float* __restrict__ out)
{
    extern __shared__ uint32_t sm[];
    float* red0 = (float*)(sm + SL0);
    float* red1 = (float*)(sm + SL1);

    const int tid = threadIdx.x, bid = blockIdx.x;
    const int mt = bid >> 5, nt = bid & 31;
    const int m0 = mt * MT, n0 = nt * NT;
    const int w = tid >> 5, lane = tid & 31;
    const int g = lane >> 2, c = lane & 3;
    const int ss = w & 1, kg = w >> 1;
    const int gtid = bid * NTHREADS + tid;
    const int srow = n0 + ss * 16 + g;

    uint32_t rank;
    asm("mov.u32 %0, %%cluster_ctarank;" : "=r"(rank));

    const uint32_t smb = (uint32_t)__cvta_generic_to_shared(sm);
    const uint32_t mbarA = smb + MBB, mbarB = mbarA + 8, mbarU = mbarA + 16, mbarP = mbarA + 24;

    const unsigned base = *((volatile unsigned*)&g_release);

    if (tid == 0) {
#pragma unroll
        for (int i = 0; i < 4; i++)
            asm volatile("mbarrier.init.shared.b64 [%0], %1;"
                         :: "r"(mbarA + i * 8), "r"(1) : "memory");
    }
    __syncthreads();
    asm volatile("barrier.cluster.arrive.aligned;" ::: "memory");
    asm volatile("barrier.cluster.wait.aligned;" ::: "memory");

    // ---- init conversions ----
    for (int jj = gtid; jj < HH * BSZ * (AD / 4); jj += NCTA * NTHREADS) {
        int a4 = jj & 31, b = (jj >> 5) & 127, t = jj >> 12;
        float4 v = *(const float4*)(u + ((size_t)b * HH + t) * AD + a4 * 4);
        int umt = b >> 5, bl = b & 31;
        int k2 = a4 * 2, o16 = k2 >> 3, c2 = k2 & 7;
        int rr = t / 3, js = t - 3 * rr;
        size_t idx = ((size_t)rr * 4 + umt) * 6144 + (size_t)js * 2048
                   + (size_t)o16 * 128 + (size_t)bl * 4 + (c2 & 3) + ((c2 & 4) ? 1024 : 0);
        *(uint2*)(g_ubuf + idx) = make_uint2(pack2(v.x, v.y), pack2(v.z, v.w));
    }
    for (int jj = gtid; jj < BSZ * (SDIM / 4); jj += NCTA * NTHREADS) {
        int s4c = jj & 255, b = jj >> 8;
        float4 v = ((const float4*)x0)[jj];
        ((float4*)out)[(size_t)b * OUT_T * (SDIM / 4) + s4c] = v;
        int xmt = b >> 5, bl = b & 31;
        int k2 = s4c * 2, o16 = k2 >> 3, c2 = k2 & 7;
        size_t idx = (size_t)xmt * 16384 + (size_t)o16 * 128 + (size_t)bl * 4
                   + (c2 & 3) + ((c2 & 4) ? XHI : 0);
        *(uint2*)(g_xbuf[0] + idx) = make_uint2(pack2(v.x, v.y), pack2(v.z, v.w));
    }
    for (int jj = gtid; jj < 512 * 1024; jj += NCTA * NTHREADS) {
        int k = jj & 1023, j2 = jj >> 10;
        int kb = k >> 5, kcol = k & 31, o16 = j2 >> 3, c2 = j2 & 7;
        g_colA[(size_t)kb * 16384 + o16 * 128 + kcol * 4 + (c2 & 3) + ((c2 & 4) ? 8192 : 0)]
            = pack2(A[(size_t)(2 * j2) * SDIM + k], A[(size_t)(2 * j2 + 1) * SDIM + k]);
    }
    for (int jj = gtid; jj < 512 * 128; jj += NCTA * NTHREADS) {
        int ku = jj & 127, j2 = jj >> 7;
        int kb = ku >> 5, kcol = ku & 31, o16 = j2 >> 3, c2 = j2 & 7;
        g_colB[(size_t)kb * 16384 + o16 * 128 + kcol * 4 + (c2 & 3) + ((c2 & 4) ? 8192 : 0)]
            = pack2(Bm[(size_t)(2 * j2) * AD + ku], Bm[(size_t)(2 * j2 + 1) * AD + ku]);
    }

    // ---- precompute A2/AB then A3/A2B (A weights in regs, scoped) ----
    {
        uint32_t axA[16][4];
#pragma unroll
        for (int i = 0; i < 16; i++) {
            int kb = kg * 256 + i * 16 + 2 * c;
            const float* r0 = A + (size_t)srow * SDIM;
            const float* r8 = A + (size_t)(srow + 8) * SDIM;
            axA[i][0] = pack2(r0[kb], r0[kb + 1]);
            axA[i][1] = pack2(r8[kb], r8[kb + 1]);
            axA[i][2] = pack2(r0[kb + 8], r0[kb + 9]);
            axA[i][3] = pack2(r8[kb + 8], r8[kb + 9]);
        }
        grid_barrier(base + 1, bid, tid);
        precomp9(axA, g_colA, g_colB, g_a2, g_ab, sm, red0, smb, mbarP,
                 mt, n0, tid, w, kg, g, c, 0);
        grid_barrier(base + 2, bid, tid);
        for (int jj = gtid; jj < 512 * 1024; jj += NCTA * NTHREADS) {
            int k = jj & 1023, j2 = jj >> 10;
            int kb = k >> 5, kcol = k & 31, o16 = j2 >> 3, c2 = j2 & 7;
            g_colA2[(size_t)kb * 16384 + o16 * 128 + kcol * 4 + (c2 & 3) + ((c2 & 4) ? 8192 : 0)]
                = pack2(g_a2[(size_t)(2 * j2) * SDIM + k], g_a2[(size_t)(2 * j2 + 1) * SDIM + k]);
        }
        for (int jj = gtid; jj < 512 * 128; jj += NCTA * NTHREADS) {
            int ku = jj & 127, j2 = jj >> 7;
            int kb = ku >> 5, kcol = ku & 31, o16 = j2 >> 3, c2 = j2 & 7;
            g_colAB[(size_t)kb * 16384 + o16 * 128 + kcol * 4 + (c2 & 3) + ((c2 & 4) ? 8192 : 0)]
                = pack2(g_ab[(size_t)(2 * j2) * AD + ku], g_ab[(size_t)(2 * j2 + 1) * AD + ku]);
        }
        grid_barrier(base + 3, bid, tid);
        precomp9(axA, g_colA2, g_colAB, g_a3, g_a2b, sm, red0, smb, mbarP,
                 mt, n0, tid, w, kg, g, c, 9);
        grid_barrier(base + 4, bid, tid);
        // A -> smem WA (thread-local spill layout, conflict-free)
#pragma unroll
        for (int i = 0; i < 16; i++)
#pragma unroll
            for (int f = 0; f < 4; f++)
                sm[WAW + w * 2048 + (i * 4 + f) * 32 + lane] = axA[i][f];
    }

    // ---- persistent weights: A3 + A2 in regs, u-family ----
    uint32_t ax3[16][4], ax2[16][4], auB[2][4], auAB[2][4], auA2B[2][4];
#pragma unroll
    for (int i = 0; i < 16; i++) {
        int kb = kg * 256 + i * 16 + 2 * c;
        const float* p0 = g_a3 + (size_t)srow * SDIM;
        const float* p8 = g_a3 + (size_t)(srow + 8) * SDIM;
        ax3[i][0] = pack2(p0[kb], p0[kb + 1]);
        ax3[i][1] = pack2(p8[kb], p8[kb + 1]);
        ax3[i][2] = pack2(p0[kb + 8], p0[kb + 9]);
        ax3[i][3] = pack2(p8[kb + 8], p8[kb + 9]);
        const float* q0 = g_a2 + (size_t)srow * SDIM;
        const float* q8 = g_a2 + (size_t)(srow + 8) * SDIM;
        ax2[i][0] = pack2(q0[kb], q0[kb + 1]);
        ax2[i][1] = pack2(q8[kb], q8[kb + 1]);
        ax2[i][2] = pack2(q0[kb + 8], q0[kb + 9]);
        ax2[i][3] = pack2(q8[kb + 8], q8[kb + 9]);
    }
#pragma unroll
    for (int jq = 0; jq < 2; jq++) {
        int kb = kg * 32 + jq * 16 + 2 * c;
        const float* r0 = Bm + (size_t)srow * AD;
        const float* r8 = Bm + (size_t)(srow + 8) * AD;
        auB[jq][0] = pack2(r0[kb], r0[kb + 1]);
        auB[jq][1] = pack2(r8[kb], r8[kb + 1]);
        auB[jq][2] = pack2(r0[kb + 8], r0[kb + 9]);
        auB[jq][3] = pack2(r8[kb + 8], r8[kb + 9]);
        const float* s0 = g_ab + (size_t)srow * AD;
        const float* s8 = g_ab + (size_t)(srow + 8) * AD;
        auAB[jq][0] = pack2(s0[kb], s0[kb + 1]);
        auAB[jq][1] = pack2(s8[kb], s8[kb + 1]);
        auAB[jq][2] = pack2(s0[kb + 8], s0[kb + 9]);
        auAB[jq][3] = pack2(s8[kb + 8], s8[kb + 9]);
        const float* t0 = g_a2b + (size_t)srow * AD;
        const float* t8 = g_a2b + (size_t)(srow + 8) * AD;
        auA2B[jq][0] = pack2(t0[kb], t0[kb + 1]);
        auA2B[jq][1] = pack2(t8[kb], t8[kb + 1]);
        auA2B[jq][2] = pack2(t0[kb + 8], t0[kb + 9]);
        auA2B[jq][3] = pack2(t8[kb + 8], t8[kb + 9]);
    }
    __syncthreads();

    // ---- bootstrap round-0 staging ----
    if (tid == 0) {
        asm volatile("fence.proxy.async;" ::: "memory");
        mbar_expect(mbarA, 32768); mbar_expect(mbarB, 32768); mbar_expect(mbarU, 24576);
        bulk_mc(smb + rank * 16384u,
                g_xbuf[0] + (size_t)mt * 16384 + (size_t)rank * 4096,
                16384, (rank & 1) ? mbarB : mbarA, 0xF);
        if (rank == 3)
            bulk_mc(smb + UWB * 4u, g_ubuf + (size_t)mt * 6144, 24576, mbarU, 0xF);
    }

    const uint32_t* xs = sm + kg * 2048 + g * 4 + c;
    const uint32_t* us = sm + UWB + kg * 256 + g * 4 + c;
    const uint32_t* wa = sm + WAW + w * 2048 + lane;
    const int rb = w * GMS + g * RS + 2 * c;

    for (int r = 0; r < NRF; r++) {
        const uint32_t par = (uint32_t)(r & 1);
        // ---- gemm3 (critical): A3 x + A2B u0 + AB u1 + B u2 ----
        float d3[4][4];
#pragma unroll
        for (int nn = 0; nn < 4; nn++)
#pragma unroll
            for (int e = 0; e < 4; e++) d3[nn][e] = 0.f;
        mbar_wait((kg >= 2) ? mbarB : mbarA, par);
#pragma unroll
        for (int i = 0; i < 16; i++)
#pragma unroll
            for (int nn = 0; nn < 4; nn++)
                mma_f16(d3[nn], ax3[i][0], ax3[i][1], ax3[i][2], ax3[i][3],
                        xs[i * 128 + nn * 32], xs[i * 128 + nn * 32 + XHI]);
        mbar_wait(mbarU, par);
#pragma unroll
        for (int jq = 0; jq < 2; jq++)
#pragma unroll
            for (int nn = 0; nn < 4; nn++) {
                int o = jq * 128 + nn * 32;
                mma_f16(d3[nn], auA2B[jq][0], auA2B[jq][1], auA2B[jq][2], auA2B[jq][3],
                        us[o], us[o + 1024]);
                mma_f16(d3[nn], auAB[jq][0], auAB[jq][1], auAB[jq][2], auAB[jq][3],
                        us[o + 2048], us[o + 3072]);
                mma_f16(d3[nn], auB[jq][0], auB[jq][1], auB[jq][2], auB[jq][3],
                        us[o + 4096], us[o + 5120]);
            }
#pragma unroll
        for (int nn = 0; nn < 4; nn++) {
            *(float2*)(red0 + rb + nn * 8) = make_float2(d3[nn][0], d3[nn][1]);
            *(float2*)(red0 + rb + 8 * RS + nn * 8) = make_float2(d3[nn][2], d3[nn][3]);
        }
        __syncthreads();
        {   // reduce3 -> out(3r+3), next state
            int b = tid >> 3, s4 = (tid & 7) * 4, ssr = s4 >> 4;
            float a3v[4] = {0.f, 0.f, 0.f, 0.f};
#pragma unroll
            for (int kk = 0; kk < 4; kk++) {
                int wb = (kk * 2 + ssr) * GMS + b;
#pragma unroll
                for (int i = 0; i < 4; i++) a3v[i] += red0[wb + ((s4 + i) & 15) * RS];
            }
            float* op = out + ((size_t)(m0 + b) * OUT_T + (3 * r + 3)) * SDIM + n0 + s4;
            *(float4*)op = make_float4(a3v[0], a3v[1], a3v[2], a3v[3]);
            int k2 = (n0 + s4) >> 1, o16 = k2 >> 3, c2 = k2 & 7;
            size_t idx = (size_t)mt * 16384 + (size_t)o16 * 128 + (size_t)b * 4
                       + (c2 & 3) + ((c2 & 4) ? XHI : 0);
            uint32_t* xp = g_xbuf[(r + 1) & 1] + idx;
            uint32_t w0 = pack2(a3v[0], a3v[1]), w1 = pack2(a3v[2], a3v[3]);
            asm volatile("st.global.cg.v2.b32 [%0], {%1,%2};"
                         :: "l"(xp), "r"(w0), "r"(w1) : "memory");
        }
        __syncthreads();

        // ---- shadow gemms: gemm1 = A x + B u0 ; gemm2 = A2 x + AB u0 + B u1 ----
        float d1[4][4], d2[4][4];
#pragma unroll
        for (int nn = 0; nn < 4; nn++)
#pragma unroll
            for (int e = 0; e < 4; e++) { d1[nn][e] = 0.f; d2[nn][e] = 0.f; }
#pragma unroll
        for (int i = 0; i < 16; i++) {
            uint32_t a0 = wa[(i * 4 + 0) * 32], a1 = wa[(i * 4 + 1) * 32];
            uint32_t a2 = wa[(i * 4 + 2) * 32], a3 = wa[(i * 4 + 3) * 32];
#pragma unroll
            for (int nn = 0; nn < 4; nn++) {
                uint32_t b0 = xs[i * 128 + nn * 32], b1 = xs[i * 128 + nn * 32 + XHI];
                mma_f16(d1[nn], a0, a1, a2, a3, b0, b1);
                mma_f16(d2[nn], ax2[i][0], ax2[i][1], ax2[i][2], ax2[i][3], b0, b1);
            }
        }
#pragma unroll
        for (int jq = 0; jq < 2; jq++)
#pragma unroll
            for (int nn = 0; nn < 4; nn++) {
                int o = jq * 128 + nn * 32;
                mma_f16(d1[nn], auB[jq][0], auB[jq][1], auB[jq][2], auB[jq][3],
                        us[o], us[o + 1024]);
                mma_f16(d2[nn], auAB[jq][0], auAB[jq][1], auAB[jq][2], auAB[jq][3],
                        us[o], us[o + 1024]);
                mma_f16(d2[nn], auB[jq][0], auB[jq][1], auB[jq][2], auB[jq][3],
                        us[o + 2048], us[o + 3072]);
            }
#pragma unroll
        for (int nn = 0; nn < 4; nn++) {
            *(float2*)(red0 + rb + nn * 8) = make_float2(d1[nn][0], d1[nn][1]);
            *(float2*)(red0 + rb + 8 * RS + nn * 8) = make_float2(d1[nn][2], d1[nn][3]);
            *(float2*)(red1 + rb + nn * 8) = make_float2(d2[nn][0], d2[nn][1]);
            *(float2*)(red1 + rb + 8 * RS + nn * 8) = make_float2(d2[nn][2], d2[nn][3]);
        }
        __threadfence();
        __syncthreads();
        if (tid == 0)   // all smem reads of round r done; x_{3r+3} in gmem
            *((volatile unsigned*)&g_flag[mt][nt][0]) = base + 5 + r;
        {   // reduce1/2 -> out(3r+1), out(3r+2)
            int b = tid >> 3, s4 = (tid & 7) * 4, ssr = s4 >> 4;
            float a1[4] = {0.f, 0.f, 0.f, 0.f}, a2v[4] = {0.f, 0.f, 0.f, 0.f};
#pragma unroll
            for (int kk = 0; kk < 4; kk++) {
                int wb = (kk * 2 + ssr) * GMS + b;
#pragma unroll
                for (int i = 0; i < 4; i++) {
                    a1[i] += red0[wb + ((s4 + i) & 15) * RS];
                    a2v[i] += red1[wb + ((s4 + i) & 15) * RS];
                }
            }
            float* op1 = out + ((size_t)(m0 + b) * OUT_T + (3 * r + 1)) * SDIM + n0 + s4;
            *(float4*)op1 = make_float4(a1[0], a1[1], a1[2], a1[3]);
            float* op2 = out + ((size_t)(m0 + b) * OUT_T + (3 * r + 2)) * SDIM + n0 + s4;
            *(float4*)op2 = make_float4(a2v[0], a2v[1], a2v[2], a2v[3]);
        }
        // ---- poll + stage round r+1 ----
        if (tid < 32) {
            unsigned want = base + 5 + r;
            while ((int)(*((volatile unsigned*)&g_flag[mt][tid][0]) - want) < 0) { }
        }
        __syncthreads();
        if (tid == 0) {
            asm volatile("fence.proxy.async;" ::: "memory");
            mbar_expect(mbarA, 32768); mbar_expect(mbarB, 32768); mbar_expect(mbarU, 24576);
            bulk_mc(smb + rank * 16384u,
                    g_xbuf[(r + 1) & 1] + (size_t)mt * 16384 + (size_t)rank * 4096,
                    16384, (rank & 1) ? mbarB : mbarA, 0xF);
            if (rank == 3)
                bulk_mc(smb + UWB * 4u,
                        g_ubuf + ((size_t)(r + 1) * 4 + mt) * 6144, 24576, mbarU, 0xF);
        }
    }

    // ---- final round (steps 511, 512): gemm1 + gemm2 only ----
    {
        const uint32_t par = (uint32_t)(NRF & 1);
        float d1[4][4], d2[4][4];
#pragma unroll
        for (int nn = 0; nn < 4; nn++)
#pragma unroll
            for (int e = 0; e < 4; e++) { d1[nn][e] = 0.f; d2[nn][e] = 0.f; }
        mbar_wait((kg >= 2) ? mbarB : mbarA, par);
#pragma unroll
        for (int i = 0; i < 16; i++) {
            uint32_t a0 = wa[(i * 4 + 0) * 32], a1 = wa[(i * 4 + 1) * 32];
            uint32_t a2 = wa[(i * 4 + 2) * 32], a3 = wa[(i * 4 + 3) * 32];
#pragma unroll
            for (int nn = 0; nn < 4; nn++) {
                uint32_t b0 = xs[i * 128 + nn * 32], b1 = xs[i * 128 + nn * 32 + XHI];
                mma_f16(d1[nn], a0, a1, a2, a3, b0, b1);
                mma_f16(d2[nn], ax2[i][0], ax2[i][1], ax2[i][2], ax2[i][3], b0, b1);
            }
        }
        mbar_wait(mbarU, par);
#pragma unroll
        for (int jq = 0; jq < 2; jq++)
#pragma unroll
            for (int nn = 0; nn < 4; nn++) {
                int o = jq * 128 + nn * 32;
                mma_f16(d1[nn], auB[jq][0], auB[jq][1], auB[jq][2], auB[jq][3],
                        us[o], us[o + 1024]);
                mma_f16(d2[nn], auAB[jq][0], auAB[jq][1], auAB[jq][2], auAB[jq][3],
                        us[o], us[o + 1024]);
                mma_f16(d2[nn], auB[jq][0], auB[jq][1], auB[jq][2], auB[jq][3],
                        us[o + 2048], us[o + 3072]);
            }
#pragma unroll
        for (int nn = 0; nn < 4; nn++) {
            *(float2*)(red0 + rb + nn * 8) = make_float2(d1[nn][0], d1[nn][1]);
            *(float2*)(red0 + rb + 8 * RS + nn * 8) = make_float2(d1[nn][2], d1[nn][3]);
            *(float2*)(red1 + rb + nn * 8) = make_float2(d2[nn][0], d2[nn][1]);
            *(float2*)(red1 + rb + 8 * RS + nn * 8) = make_float2(d2[nn][2], d2[nn][3]);
        }
        __syncthreads();
        int b = tid >> 3, s4 = (tid & 7) * 4, ssr = s4 >> 4;
        float a1[4] = {0.f, 0.f, 0.f, 0.f}, a2v[4] = {0.f, 0.f, 0.f, 0.f};
#pragma unroll
        for (int kk = 0; kk < 4; kk++) {
            int wb = (kk * 2 + ssr) * GMS + b;
#pragma unroll
            for (int i = 0; i < 4; i++) {
                a1[i] += red0[wb + ((s4 + i) & 15) * RS];
                a2v[i] += red1[wb + ((s4 + i) & 15) * RS];
            }
        }
        float* op1 = out + ((size_t)(m0 + b) * OUT_T + 511) * SDIM + n0 + s4;
        *(float4*)op1 = make_float4(a1[0], a1[1], a1[2], a1[3]);
        float* op2 = out + ((size_t)(m0 + b) * OUT_T + 512) * SDIM + n0 + s4;
        *(float4*)op2 = make_float4(a2v[0], a2v[1], a2v[2], a2v[3]);
    }

    if (bid == 0 && tid == 0) {
        __threadfence();
        *((volatile unsigned*)&g_release) = base + 5 + NRF;
    }
}

extern "C" void kernel_launch(void* const* d_in, const int* in_sizes, int n_in,
                              void* d_out, int out_size)
{
    const float* x0 = (const float*)d_in[0];
    const float* u  = (const float*)d_in[1];
    const float* A  = (const float*)d_in[2];
    const float* Bm = (const float*)d_in[3];
    float* out = (float*)d_out;

    cudaFuncSetAttribute(ssm_v16_kernel,
                         cudaFuncAttributeMaxDynamicSharedMemorySize, SMEM_BYTES);

    ssm_v16_kernel<<<NCTA, NTHREADS, SMEM_BYTES>>>(x0, u, A, Bm, out);
}